// round 8
// baseline (speedup 1.0000x reference)
#include <cuda_runtime.h>

#define T_STEPS 8192
#define MDIM    1024
#define INDIM   1024
#define XCOLS   5120
#define NCTA    128
#define NTHR    512
#define CELLS   8      // memory cells owned per CTA (1024/128)

// ---------------- scratch (static device globals; no allocation) -------------
__device__ float    g_xproj[(size_t)T_STEPS * XCOLS];   // 160 MB
__device__ float    g_hpay[2][NCTA][CELLS];              // h payload, double-buffered by step parity
__device__ float    g_apay[2][NCTA][CELLS];              // a payload
__device__ unsigned g_htag[NCTA];                        // monotonic per-producer tags
__device__ unsigned g_atag[NCTA];
__device__ unsigned g_epoch;                             // completed scan launches

// ---- memory-order helpers -----------------------------------------------------
__device__ __forceinline__ void st_relaxed_f32(float* p, float v) {
    asm volatile("st.relaxed.gpu.global.f32 [%0], %1;" :: "l"(p), "f"(v) : "memory");
}
__device__ __forceinline__ void st_release_u32(unsigned* p, unsigned v) {
    asm volatile("st.release.gpu.global.u32 [%0], %1;" :: "l"(p), "r"(v) : "memory");
}
__device__ __forceinline__ unsigned ld_acquire_u32(const unsigned* p) {
    unsigned v;
    asm volatile("ld.acquire.gpu.global.u32 %0, [%1];" : "=r"(v) : "l"(p) : "memory");
    return v;
}
__device__ __forceinline__ float4 ld_cg_f4(const float4* p) {
    float4 v;
    asm volatile("ld.global.cg.v4.f32 {%0,%1,%2,%3}, [%4];"
                 : "=f"(v.x), "=f"(v.y), "=f"(v.z), "=f"(v.w) : "l"(p));
    return v;
}

// ---- XLA-matched transcendentals ---------------------------------------------
__device__ __forceinline__ float xla_tanh(float x) {
    float xc = fminf(fmaxf(x, -9.0f), 9.0f);
    float x2 = xc * xc;
    float p = fmaf(x2, -2.76076847742355e-16f, 2.00018790482477e-13f);
    p = fmaf(x2, p, -8.60467152213735e-11f);
    p = fmaf(x2, p,  5.12229709037114e-08f);
    p = fmaf(x2, p,  1.48572235717979e-05f);
    p = fmaf(x2, p,  6.37261928875436e-04f);
    p = fmaf(x2, p,  4.89352455891786e-03f);
    float num = __fmul_rn(xc, p);
    float q = fmaf(x2, 1.19825839466702e-06f, 1.18534705686654e-04f);
    q = fmaf(x2, q, 2.26843463243900e-03f);
    q = fmaf(x2, q, 4.89352518554385e-03f);
    return (fabsf(x) < 4.0e-4f) ? x : __fdiv_rn(num, q);
}
__device__ __forceinline__ float xla_sigmoid(float x) {
    float e;
    asm("ex2.approx.f32 %0, %1;" : "=f"(e) : "f"(-x * 1.4426950408889634f));
    return __fdiv_rn(1.0f, __fadd_rn(1.0f, e));
}

// ---------------- Kernel 1: xproj = inputs @ Wx^T + bx  (NT SGEMM, fp32) -----
__global__ void __launch_bounds__(256) xproj_gemm(
    const float* __restrict__ A,
    const float* __restrict__ B,
    const float* __restrict__ bias)
{
    __shared__ float As[8][128];
    __shared__ float Bs[8][128];

    int tid = threadIdx.x;
    int tx  = tid & 15, ty = tid >> 4;
    int m0  = blockIdx.y * 128, n0 = blockIdx.x * 128;
    int lrow = tid >> 1, lk = (tid & 1) * 4;

    const float* Ap = A + (size_t)(m0 + lrow) * INDIM + lk;
    const float* Bp = B + (size_t)(n0 + lrow) * INDIM + lk;

    float acc[8][8];
#pragma unroll
    for (int i = 0; i < 8; i++)
#pragma unroll
        for (int j = 0; j < 8; j++) acc[i][j] = 0.0f;

    for (int k0 = 0; k0 < INDIM; k0 += 8) {
        float4 av = *(const float4*)(Ap + k0);
        float4 bv = *(const float4*)(Bp + k0);
        As[lk + 0][lrow] = av.x; As[lk + 1][lrow] = av.y;
        As[lk + 2][lrow] = av.z; As[lk + 3][lrow] = av.w;
        Bs[lk + 0][lrow] = bv.x; Bs[lk + 1][lrow] = bv.y;
        Bs[lk + 2][lrow] = bv.z; Bs[lk + 3][lrow] = bv.w;
        __syncthreads();
#pragma unroll
        for (int kk = 0; kk < 8; kk++) {
            float a[8], b[8];
            *(float4*)&a[0] = *(const float4*)&As[kk][ty * 8];
            *(float4*)&a[4] = *(const float4*)&As[kk][ty * 8 + 4];
            *(float4*)&b[0] = *(const float4*)&Bs[kk][tx * 8];
            *(float4*)&b[4] = *(const float4*)&Bs[kk][tx * 8 + 4];
#pragma unroll
            for (int i = 0; i < 8; i++)
#pragma unroll
                for (int j = 0; j < 8; j++) acc[i][j] += a[i] * b[j];
        }
        __syncthreads();
    }

    float bb[8];
#pragma unroll
    for (int j = 0; j < 8; j++) bb[j] = bias[n0 + tx * 8 + j];
#pragma unroll
    for (int i = 0; i < 8; i++) {
        float* crow = g_xproj + (size_t)(m0 + ty * 8 + i) * XCOLS + n0 + tx * 8;
        float4 v0 = make_float4(__fadd_rn(acc[i][0], bb[0]), __fadd_rn(acc[i][1], bb[1]),
                                __fadd_rn(acc[i][2], bb[2]), __fadd_rn(acc[i][3], bb[3]));
        float4 v1 = make_float4(__fadd_rn(acc[i][4], bb[4]), __fadd_rn(acc[i][5], bb[5]),
                                __fadd_rn(acc[i][6], bb[6]), __fadd_rn(acc[i][7], bb[7]));
        *(float4*)crow       = v0;
        *(float4*)(crow + 4) = v1;
    }
}

// ---------------- Kernel 2: persistent recurrent scan (dataflow sync) --------
// 128 CTAs x 512 threads. CTA owns cells [8*cta, 8*cta+8).
// Warp w (0..15) owns Wh slice rows 2w, 2w+1 (row s = gate*8 + cell).
// Warps 0..7 additionally own Wm row = cell w (full row, order-identical dot).
__global__ void __launch_bounds__(NTHR, 1) ulstm_scan(
    const float* __restrict__ Wh, const float* __restrict__ bh,
    const float* __restrict__ Wm, const float* __restrict__ bm,
    float* __restrict__ out)
{
    __shared__ float h_s[MDIM];
    __shared__ float a_s[MDIM];
    __shared__ float hp_s[32];
    __shared__ float gate_s[32];   // i(0..7) o(8..15) z(16..23) f(24..31)
    __shared__ float gu_s[CELLS];
    __shared__ float tc_s[CELLS];  // tanh(c) carried from previous step
    __shared__ float c_s[CELLS];
    __shared__ float bh_s[32];
    __shared__ float bm_s[CELLS];

    const int tid = threadIdx.x;
    const int w   = tid >> 5;
    const int l   = tid & 31;
    const int cta = blockIdx.x;

    const unsigned base = ld_acquire_u32(&g_epoch) * 32768u;   // > T_STEPS+1 stride

    // ---- weights into registers (persist across all 8192 steps) ----
    float4 wa[2][8];
#pragma unroll
    for (int r = 0; r < 2; r++) {
        int s   = 2 * w + r;
        int row = (s >> 3) * MDIM + cta * CELLS + (s & 7);
        const float4* src = (const float4*)(Wh + (size_t)row * MDIM);
#pragma unroll
        for (int c4 = 0; c4 < 8; c4++) wa[r][c4] = src[c4 * 32 + l];
    }
    float4 wmr[8];
    if (w < 8) {
        int row = cta * CELLS + w;
        const float4* src = (const float4*)(Wm + (size_t)row * MDIM);
#pragma unroll
        for (int c4 = 0; c4 < 8; c4++) wmr[c4] = src[c4 * 32 + l];
    }
    if (tid < 32) bh_s[tid] = bh[(tid >> 3) * MDIM + cta * CELLS + (tid & 7)];
    if (tid < CELLS) { bm_s[tid] = bm[cta * CELLS + tid]; c_s[tid] = 0.0f; tc_s[tid] = 0.0f; }
    __syncthreads();

    for (int t = 0; t < T_STEPS; t++) {
        // prefetch this step's xproj gate inputs (warp 0; consumed after phase A)
        float xg = 0.f, uxr = 0.f;
        if (tid < 32) {
            const float* xr = g_xproj + (size_t)t * XCOLS + (tid >> 3) * MDIM + cta * CELLS + (tid & 7);
            xg = xr[0];
            if (tid < 8) uxr = xr[4 * MDIM];
        }

        // ---------- h exchange + Phase A: hp = Wh @ h + bh ----------
        if (t > 0) {
            if (tid < 128) {   // one poller per producer
                const unsigned want = base + (unsigned)t;          // h(t-1) tag
                while (ld_acquire_u32(&g_htag[tid]) < want) { }
                const float4* pp = (const float4*)&g_hpay[(t - 1) & 1][tid][0];
                float4 p0 = ld_cg_f4(pp);
                float4 p1 = ld_cg_f4(pp + 1);
                ((float4*)h_s)[tid * 2]     = p0;
                ((float4*)h_s)[tid * 2 + 1] = p1;
            }
            __syncthreads();
            float acc0 = 0.f, acc1 = 0.f;
#pragma unroll
            for (int c4 = 0; c4 < 8; c4++) {
                float4 hv = ((const float4*)h_s)[c4 * 32 + l];
                acc0 += wa[0][c4].x * hv.x + wa[0][c4].y * hv.y + wa[0][c4].z * hv.z + wa[0][c4].w * hv.w;
                acc1 += wa[1][c4].x * hv.x + wa[1][c4].y * hv.y + wa[1][c4].z * hv.z + wa[1][c4].w * hv.w;
            }
#pragma unroll
            for (int off = 16; off > 0; off >>= 1) {
                acc0 += __shfl_xor_sync(0xffffffffu, acc0, off);
                acc1 += __shfl_xor_sync(0xffffffffu, acc1, off);
            }
            if (l == 0) {
                hp_s[2 * w + 0] = __fadd_rn(acc0, bh_s[2 * w + 0]);
                hp_s[2 * w + 1] = __fadd_rn(acc1, bh_s[2 * w + 1]);
            }
        } else {
            if (tid < 32) hp_s[tid] = bh_s[tid];   // h0 = 0 -> hp = bh
        }
        __syncthreads();

        // ---------- gates (warp 0) + a publish; a pollers in parallel --------
        if (tid < 32) {
            if (tid < 8) gu_s[tid] = uxr;
            float s = xla_sigmoid(__fadd_rn(xg, hp_s[tid]));
            gate_s[tid] = s;
            __syncwarp();
            if (tid < 8) {
                float a_ = __fmul_rn(gate_s[16 + tid], tc_s[tid]);
                st_relaxed_f32(&g_apay[t & 1][cta][tid], a_);
            }
            __syncwarp();
            if (tid == 0) st_release_u32(&g_atag[cta], base + (unsigned)t + 1u);
        }
        if (tid >= 128 && tid < 256) {
            const int i = tid - 128;
            const unsigned want = base + (unsigned)t + 1u;
            while (ld_acquire_u32(&g_atag[i]) < want) { }
            const float4* pp = (const float4*)&g_apay[t & 1][i][0];
            float4 p0 = ld_cg_f4(pp);
            float4 p1 = ld_cg_f4(pp + 1);
            ((float4*)a_s)[i * 2]     = p0;
            ((float4*)a_s)[i * 2 + 1] = p1;
        }
        __syncthreads();

        // ---------- Phase B (warps 0-7): u = tanh(ux + Wm@a + bm); update ----
        if (w < 8) {
            float acc = 0.f;
#pragma unroll
            for (int c4 = 0; c4 < 8; c4++) {
                float4 av = ((const float4*)a_s)[c4 * 32 + l];
                acc += wmr[c4].x * av.x + wmr[c4].y * av.y + wmr[c4].z * av.z + wmr[c4].w * av.w;
            }
#pragma unroll
            for (int off = 16; off > 0; off >>= 1)
                acc += __shfl_xor_sync(0xffffffffu, acc, off);

            if (l == 0) {
                float u  = xla_tanh(__fadd_rn(__fadd_rn(gu_s[w], acc), bm_s[w]));
                float c2 = __fadd_rn(__fmul_rn(gate_s[w], u), __fmul_rn(gate_s[24 + w], c_s[w]));
                float th = xla_tanh(c2);
                float h2 = __fmul_rn(gate_s[8 + w], th);
                c_s[w]  = c2;
                tc_s[w] = th;
                if (t == T_STEPS - 1) {
                    out[cta * CELLS + w]        = c2;
                    out[MDIM + cta * CELLS + w] = h2;
                } else {
                    st_relaxed_f32(&g_hpay[t & 1][cta][w], h2);
                }
            }
        }
        __syncthreads();   // orders warps 0-7's h stores before tid 0's release
        if (t < T_STEPS - 1 && tid == 0)
            st_release_u32(&g_htag[cta], base + (unsigned)t + 1u);
    }

    // one epoch bump per launch (safe: all CTAs read g_epoch at start, and no
    // CTA can finish step 0 before every CTA has started)
    if (cta == 0 && tid == 0)
        asm volatile("red.relaxed.gpu.global.add.u32 [%0], 1;" :: "l"(&g_epoch) : "memory");
}

// ---------------- launch ------------------------------------------------------
extern "C" void kernel_launch(void* const* d_in, const int* in_sizes, int n_in,
                              void* d_out, int out_size)
{
    const float* inputs = (const float*)d_in[0];
    const float* Wx     = (const float*)d_in[1];
    const float* bx     = (const float*)d_in[2];
    const float* Wh     = (const float*)d_in[3];
    const float* bh     = (const float*)d_in[4];
    const float* Wm     = (const float*)d_in[5];
    const float* bm     = (const float*)d_in[6];
    float* out = (float*)d_out;

    dim3 ggrid(XCOLS / 128, T_STEPS / 128);   // (40, 64)
    xproj_gemm<<<ggrid, 256>>>(inputs, Wx, bx);

    ulstm_scan<<<NCTA, NTHR>>>(Wh, bh, Wm, bm, out);
}

// round 10
// speedup vs baseline: 2.5616x; 2.5616x over previous
#include <cuda_runtime.h>

#define T_STEPS 8192
#define MDIM    1024
#define INDIM   1024
#define XCOLS   5120
#define NCTA    128
#define NTHR    256
#define CELLS   8      // memory cells owned per CTA (1024/128)

// ---------------- scratch (static device globals; no allocation) -------------
__device__ float g_xproj[(size_t)T_STEPS * XCOLS];                 // 160 MB
__device__ __align__(16) unsigned long long g_hpk[MDIM];           // {tag:u32, val:f32}
__device__ __align__(16) unsigned long long g_apk[MDIM];
__device__ unsigned g_epoch;                                       // completed scan launches

// ---- packet helpers: tag travels WITH data in one 8B word ------------------
// Strong (morally-strong) atomics: release store / acquire load guarantee
// single-copy atomicity of the 8B word — no tag/value tearing.
__device__ __forceinline__ void st_pkt(unsigned long long* p, float v, unsigned tag) {
    unsigned long long pk = ((unsigned long long)tag << 32) |
                            (unsigned long long)__float_as_uint(v);
    asm volatile("st.release.gpu.global.b64 [%0], %1;" :: "l"(p), "l"(pk) : "memory");
}
__device__ __forceinline__ unsigned long long ld_pkt(const unsigned long long* p) {
    unsigned long long v;
    asm volatile("ld.acquire.gpu.global.b64 %0, [%1];" : "=l"(v) : "l"(p) : "memory");
    return v;
}
// Poll 4 consecutive packets until all carry tag >= want; deposit values.
__device__ __forceinline__ void poll4(const unsigned long long* p, unsigned want,
                                      float* dst) {
    unsigned long long a, b, c, d;
    do {
        a = ld_pkt(p + 0);
        b = ld_pkt(p + 1);
        c = ld_pkt(p + 2);
        d = ld_pkt(p + 3);
    } while ((unsigned)(a >> 32) < want || (unsigned)(b >> 32) < want ||
             (unsigned)(c >> 32) < want || (unsigned)(d >> 32) < want);
    dst[0] = __uint_as_float((unsigned)a);
    dst[1] = __uint_as_float((unsigned)b);
    dst[2] = __uint_as_float((unsigned)c);
    dst[3] = __uint_as_float((unsigned)d);
}

// ---- XLA-matched transcendentals ---------------------------------------------
__device__ __forceinline__ float xla_tanh(float x) {
    float xc = fminf(fmaxf(x, -9.0f), 9.0f);
    float x2 = xc * xc;
    float p = fmaf(x2, -2.76076847742355e-16f, 2.00018790482477e-13f);
    p = fmaf(x2, p, -8.60467152213735e-11f);
    p = fmaf(x2, p,  5.12229709037114e-08f);
    p = fmaf(x2, p,  1.48572235717979e-05f);
    p = fmaf(x2, p,  6.37261928875436e-04f);
    p = fmaf(x2, p,  4.89352455891786e-03f);
    float num = __fmul_rn(xc, p);
    float q = fmaf(x2, 1.19825839466702e-06f, 1.18534705686654e-04f);
    q = fmaf(x2, q, 2.26843463243900e-03f);
    q = fmaf(x2, q, 4.89352518554385e-03f);
    return (fabsf(x) < 4.0e-4f) ? x : __fdiv_rn(num, q);
}
__device__ __forceinline__ float xla_sigmoid(float x) {
    float e;
    asm("ex2.approx.f32 %0, %1;" : "=f"(e) : "f"(-x * 1.4426950408889634f));
    return __fdiv_rn(1.0f, __fadd_rn(1.0f, e));
}

// ---------------- Kernel 1: xproj = inputs @ Wx^T + bx  (NT SGEMM, fp32) -----
__global__ void __launch_bounds__(256) xproj_gemm(
    const float* __restrict__ A,
    const float* __restrict__ B,
    const float* __restrict__ bias)
{
    __shared__ float As[8][128];
    __shared__ float Bs[8][128];

    int tid = threadIdx.x;
    int tx  = tid & 15, ty = tid >> 4;
    int m0  = blockIdx.y * 128, n0 = blockIdx.x * 128;
    int lrow = tid >> 1, lk = (tid & 1) * 4;

    const float* Ap = A + (size_t)(m0 + lrow) * INDIM + lk;
    const float* Bp = B + (size_t)(n0 + lrow) * INDIM + lk;

    float acc[8][8];
#pragma unroll
    for (int i = 0; i < 8; i++)
#pragma unroll
        for (int j = 0; j < 8; j++) acc[i][j] = 0.0f;

    for (int k0 = 0; k0 < INDIM; k0 += 8) {
        float4 av = *(const float4*)(Ap + k0);
        float4 bv = *(const float4*)(Bp + k0);
        As[lk + 0][lrow] = av.x; As[lk + 1][lrow] = av.y;
        As[lk + 2][lrow] = av.z; As[lk + 3][lrow] = av.w;
        Bs[lk + 0][lrow] = bv.x; Bs[lk + 1][lrow] = bv.y;
        Bs[lk + 2][lrow] = bv.z; Bs[lk + 3][lrow] = bv.w;
        __syncthreads();
#pragma unroll
        for (int kk = 0; kk < 8; kk++) {
            float a[8], b[8];
            *(float4*)&a[0] = *(const float4*)&As[kk][ty * 8];
            *(float4*)&a[4] = *(const float4*)&As[kk][ty * 8 + 4];
            *(float4*)&b[0] = *(const float4*)&Bs[kk][tx * 8];
            *(float4*)&b[4] = *(const float4*)&Bs[kk][tx * 8 + 4];
#pragma unroll
            for (int i = 0; i < 8; i++)
#pragma unroll
                for (int j = 0; j < 8; j++) acc[i][j] += a[i] * b[j];
        }
        __syncthreads();
    }

    float bb[8];
#pragma unroll
    for (int j = 0; j < 8; j++) bb[j] = bias[n0 + tx * 8 + j];
#pragma unroll
    for (int i = 0; i < 8; i++) {
        float* crow = g_xproj + (size_t)(m0 + ty * 8 + i) * XCOLS + n0 + tx * 8;
        float4 v0 = make_float4(__fadd_rn(acc[i][0], bb[0]), __fadd_rn(acc[i][1], bb[1]),
                                __fadd_rn(acc[i][2], bb[2]), __fadd_rn(acc[i][3], bb[3]));
        float4 v1 = make_float4(__fadd_rn(acc[i][4], bb[4]), __fadd_rn(acc[i][5], bb[5]),
                                __fadd_rn(acc[i][6], bb[6]), __fadd_rn(acc[i][7], bb[7]));
        *(float4*)crow       = v0;
        *(float4*)(crow + 4) = v1;
    }
}

// ---------------- Kernel 2: persistent recurrent scan (packet dataflow) ------
// 128 CTAs x 256 threads (R7 compute structure: ~232 regs, no spill).
// Warp w (0..7) owns Wh slice rows 4w..4w+3 (row s = gate*8 + cell) and Wm row w.
// Exchange: 8B {tag,value} packets via release/acquire atomics.
__global__ void __launch_bounds__(NTHR, 1) ulstm_scan(
    const float* __restrict__ Wh, const float* __restrict__ bh,
    const float* __restrict__ Wm, const float* __restrict__ bm,
    float* __restrict__ out)
{
    __shared__ __align__(16) float h_s[MDIM];
    __shared__ __align__(16) float a_s[MDIM];
    __shared__ float hp_s[32];
    __shared__ float gate_s[32];   // i(0..7) o(8..15) z(16..23) f(24..31)
    __shared__ float gu_s[CELLS];
    __shared__ float tc_s[CELLS];  // tanh(c) carried from previous step
    __shared__ float c_s[CELLS];
    __shared__ float bh_s[32];
    __shared__ float bm_s[CELLS];

    const int tid = threadIdx.x;
    const int w   = tid >> 5;
    const int l   = tid & 31;
    const int cta = blockIdx.x;

    const unsigned base = (*((volatile unsigned*)&g_epoch)) * 32768u;  // tag stride > T+1

    // ---- weights into registers (persist across all 8192 steps) ----
    float4 wa[4][8];
#pragma unroll
    for (int r = 0; r < 4; r++) {
        int s   = 4 * w + r;
        int row = (s >> 3) * MDIM + cta * CELLS + (s & 7);
        const float4* src = (const float4*)(Wh + (size_t)row * MDIM);
#pragma unroll
        for (int c4 = 0; c4 < 8; c4++) wa[r][c4] = src[c4 * 32 + l];
    }
    float4 wmr[8];
    {
        int row = cta * CELLS + w;
        const float4* src = (const float4*)(Wm + (size_t)row * MDIM);
#pragma unroll
        for (int c4 = 0; c4 < 8; c4++) wmr[c4] = src[c4 * 32 + l];
    }
    if (tid < 32) bh_s[tid] = bh[(tid >> 3) * MDIM + cta * CELLS + (tid & 7)];
    if (tid < CELLS) { bm_s[tid] = bm[cta * CELLS + tid]; c_s[tid] = 0.0f; tc_s[tid] = 0.0f; }
    __syncthreads();

    for (int t = 0; t < T_STEPS; t++) {
        // prefetch this step's xproj gate inputs (warp 0; consumed after phase A)
        float xg = 0.f, uxr = 0.f;
        if (tid < 32) {
            const float* xr = g_xproj + (size_t)t * XCOLS + (tid >> 3) * MDIM + cta * CELLS + (tid & 7);
            xg = xr[0];
            if (tid < 8) uxr = xr[4 * MDIM];
        }

        // ---------- h packets -> smem, then Phase A: hp = Wh @ h + bh --------
        if (t > 0) {
            poll4(g_hpk + tid * 4, base + (unsigned)t, h_s + tid * 4);
            __syncthreads();
            float acc0 = 0.f, acc1 = 0.f, acc2 = 0.f, acc3 = 0.f;
#pragma unroll
            for (int c4 = 0; c4 < 8; c4++) {
                float4 hv = ((const float4*)h_s)[c4 * 32 + l];
                acc0 += wa[0][c4].x * hv.x + wa[0][c4].y * hv.y + wa[0][c4].z * hv.z + wa[0][c4].w * hv.w;
                acc1 += wa[1][c4].x * hv.x + wa[1][c4].y * hv.y + wa[1][c4].z * hv.z + wa[1][c4].w * hv.w;
                acc2 += wa[2][c4].x * hv.x + wa[2][c4].y * hv.y + wa[2][c4].z * hv.z + wa[2][c4].w * hv.w;
                acc3 += wa[3][c4].x * hv.x + wa[3][c4].y * hv.y + wa[3][c4].z * hv.z + wa[3][c4].w * hv.w;
            }
#pragma unroll
            for (int off = 16; off > 0; off >>= 1) {
                acc0 += __shfl_xor_sync(0xffffffffu, acc0, off);
                acc1 += __shfl_xor_sync(0xffffffffu, acc1, off);
                acc2 += __shfl_xor_sync(0xffffffffu, acc2, off);
                acc3 += __shfl_xor_sync(0xffffffffu, acc3, off);
            }
            if (l == 0) {
                hp_s[4 * w + 0] = __fadd_rn(acc0, bh_s[4 * w + 0]);
                hp_s[4 * w + 1] = __fadd_rn(acc1, bh_s[4 * w + 1]);
                hp_s[4 * w + 2] = __fadd_rn(acc2, bh_s[4 * w + 2]);
                hp_s[4 * w + 3] = __fadd_rn(acc3, bh_s[4 * w + 3]);
            }
        } else {
            if (tid < 32) hp_s[tid] = bh_s[tid];   // h0 = 0 -> hp = bh
        }
        __syncthreads();

        // ---------- gates (warp 0) + a publish; all threads then poll a ------
        const unsigned wantA = base + (unsigned)t + 1u;
        if (tid < 32) {
            if (tid < 8) gu_s[tid] = uxr;
            float s = xla_sigmoid(__fadd_rn(xg, hp_s[tid]));
            gate_s[tid] = s;
            __syncwarp();
            if (tid < 8) {
                float a_ = __fmul_rn(gate_s[16 + tid], tc_s[tid]);
                st_pkt(&g_apk[cta * CELLS + tid], a_, wantA);
            }
        }
        poll4(g_apk + tid * 4, wantA, a_s + tid * 4);
        __syncthreads();

        // ---------- Phase B: u = tanh(ux + Wm@a + bm); state update ----------
        float acc = 0.f;
#pragma unroll
        for (int c4 = 0; c4 < 8; c4++) {
            float4 av = ((const float4*)a_s)[c4 * 32 + l];
            acc += wmr[c4].x * av.x + wmr[c4].y * av.y + wmr[c4].z * av.z + wmr[c4].w * av.w;
        }
#pragma unroll
        for (int off = 16; off > 0; off >>= 1)
            acc += __shfl_xor_sync(0xffffffffu, acc, off);

        if (l == 0) {
            float u  = xla_tanh(__fadd_rn(__fadd_rn(gu_s[w], acc), bm_s[w]));
            float c2 = __fadd_rn(__fmul_rn(gate_s[w], u), __fmul_rn(gate_s[24 + w], c_s[w]));
            float th = xla_tanh(c2);
            float h2 = __fmul_rn(gate_s[8 + w], th);
            c_s[w]  = c2;
            tc_s[w] = th;    // reused next step: a = z * tanh(c)
            if (t == T_STEPS - 1) {
                out[cta * CELLS + w]        = c2;
                out[MDIM + cta * CELLS + w] = h2;
            } else {
                st_pkt(&g_hpk[cta * CELLS + w], h2, base + (unsigned)t + 1u);
            }
        }
        // next iteration's poll4 + __syncthreads provide all further ordering
    }

    // one epoch bump per launch (all CTAs read g_epoch before any packet of this
    // launch can be produced; replays are stream-ordered)
    if (cta == 0 && tid == 0)
        asm volatile("red.relaxed.gpu.global.add.u32 [%0], 1;" :: "l"(&g_epoch) : "memory");
}

// ---------------- launch ------------------------------------------------------
extern "C" void kernel_launch(void* const* d_in, const int* in_sizes, int n_in,
                              void* d_out, int out_size)
{
    const float* inputs = (const float*)d_in[0];
    const float* Wx     = (const float*)d_in[1];
    const float* bx     = (const float*)d_in[2];
    const float* Wh     = (const float*)d_in[3];
    const float* bh     = (const float*)d_in[4];
    const float* Wm     = (const float*)d_in[5];
    const float* bm     = (const float*)d_in[6];
    float* out = (float*)d_out;

    dim3 ggrid(XCOLS / 128, T_STEPS / 128);   // (40, 64)
    xproj_gemm<<<ggrid, 256>>>(inputs, Wx, bx);

    ulstm_scan<<<NCTA, NTHR>>>(Wh, bh, Wm, bm, out);
}